// round 8
// baseline (speedup 1.0000x reference)
#include <cuda_runtime.h>
#include <cuda_fp16.h>
#include <cstddef>

// SumLayer: out[nids[n], :] = log( sum_e params[pids[n,e]] * exp(element_mars[cids[n,e], :]) )
// N=32768, E=32, B=256, element_mars [65536, 256] fp32.
//
// v5: gather is at the chip-wide LTS (~14 TB/s) ceiling -> hide the DRAM-bound
// exp pass under it. Batch is split into two 128-column chunks; the middle
// launch interleaves exp(chunk1) CTAs (DRAM-bound) with gather(chunk0) CTAs
// (L2-bound) by blockIdx parity so both run concurrently on one stream.

constexpr int E         = 32;
constexpr int B         = 256;
constexpr int ROWS      = 65536;
constexpr int NPC       = 8;          // nodes per CTA (1 warp per node)
constexpr int HALF_COLS = 128;        // batch columns per chunk

union Vec8h { uint4 u; __half2 h[4]; };
union Vec4h { uint2 u; __half2 h[2]; };

// fp16 scratch: exp(element_mars), row-major [ROWS][B] halves = 33.5 MB.
__device__ uint4 g_exp[(size_t)ROWS * B / 8];

// ---- exp for one 128-column chunk: thread handles 8 cols of one row ----
__device__ __forceinline__ void exp_chunk(const float* __restrict__ em,
                                          int chunk, int sub, int tid)
{
    const int t    = sub * 256 + tid;       // 0 .. ROWS*16-1
    const int row  = t >> 4;
    const int slot = t & 15;                // 16 uint4-slots per chunk-row
    if (row >= ROWS) return;

    const float4* src = reinterpret_cast<const float4*>(em)
                      + (size_t)row * (B / 4) + chunk * (HALF_COLS / 4) + slot * 2;
    const float4 v0 = src[0];
    const float4 v1 = src[1];
    Vec8h r;
    r.h[0] = __floats2half2_rn(__expf(v0.x), __expf(v0.y));
    r.h[1] = __floats2half2_rn(__expf(v0.z), __expf(v0.w));
    r.h[2] = __floats2half2_rn(__expf(v1.x), __expf(v1.y));
    r.h[3] = __floats2half2_rn(__expf(v1.z), __expf(v1.w));
    g_exp[(size_t)row * (B / 8) + chunk * (HALF_COLS / 8) + slot] = r.u;
}

// ---- gather-sum + log for one 128-column chunk: warp per node, 4 cols/lane ----
__device__ __forceinline__ void gather_chunk(
    const float* __restrict__ params,
    const int*   __restrict__ nids,
    const int*   __restrict__ cids,
    const int*   __restrict__ pids,
    float*       __restrict__ out,
    int n_nodes, int chunk, int first_node, int tid)
{
    __shared__ int2 s_cw[NPC][E];           // {cid, weight-bits} pairs

    const int ln   = tid >> 5;
    const int lane = tid & 31;
    const int n    = first_node + ln;

    if (n < n_nodes) {
        const size_t idx = (size_t)n * E + lane;
        s_cw[ln][lane] = make_int2(cids[idx],
                                   __float_as_int(__ldg(params + pids[idx])));
    }
    __syncwarp();
    if (n >= n_nodes) return;

    // Row = B/4 = 64 uint2; this chunk covers 32 of them; lane owns one (8B).
    const uint2* g2 = reinterpret_cast<const uint2*>(g_exp)
                    + chunk * (HALF_COLS / 4) + lane;

    float a0 = 0.f, a1 = 0.f, a2 = 0.f, a3 = 0.f;
#pragma unroll
    for (int e = 0; e < E; ++e) {
        const int2  cw = s_cw[ln][e];       // warp-uniform LDS.64 broadcast
        const float w  = __int_as_float(cw.y);
        Vec4h v;
        v.u = g2[(size_t)cw.x * (B / 4)];
        const float2 f0 = __half22float2(v.h[0]);
        const float2 f1 = __half22float2(v.h[1]);
        a0 = fmaf(w, f0.x, a0);  a1 = fmaf(w, f0.y, a1);
        a2 = fmaf(w, f1.x, a2);  a3 = fmaf(w, f1.y, a3);
    }

    const int nid = nids[n];                // warp-uniform broadcast
    float4 o;
    o.x = __logf(fmaxf(a0, 1e-10f));
    o.y = __logf(fmaxf(a1, 1e-10f));
    o.z = __logf(fmaxf(a2, 1e-10f));
    o.w = __logf(fmaxf(a3, 1e-10f));
    *reinterpret_cast<float4*>(out + (size_t)nid * B + chunk * HALF_COLS + lane * 4) = o;
}

// ---------------- kernels ----------------
__global__ __launch_bounds__(256, 8) void exp0_kernel(const float* __restrict__ em)
{
    exp_chunk(em, 0, blockIdx.x, threadIdx.x);
}

// Middle launch: odd CTAs stream exp(chunk 1) from DRAM while even CTAs run
// the L2-bound gather(chunk 0). Interleaved so both roles fill every wave.
__global__ __launch_bounds__(256, 8) void mix_kernel(
    const float* __restrict__ em,
    const float* __restrict__ params,
    const int*   __restrict__ nids,
    const int*   __restrict__ cids,
    const int*   __restrict__ pids,
    float*       __restrict__ out,
    int n_nodes)
{
    if (blockIdx.x & 1)
        exp_chunk(em, 1, blockIdx.x >> 1, threadIdx.x);
    else
        gather_chunk(params, nids, cids, pids, out, n_nodes, 0,
                     (blockIdx.x >> 1) * NPC, threadIdx.x);
}

__global__ __launch_bounds__(256, 8) void gather1_kernel(
    const float* __restrict__ params,
    const int*   __restrict__ nids,
    const int*   __restrict__ cids,
    const int*   __restrict__ pids,
    float*       __restrict__ out,
    int n_nodes)
{
    gather_chunk(params, nids, cids, pids, out, n_nodes, 1,
                 blockIdx.x * NPC, threadIdx.x);
}

extern "C" void kernel_launch(void* const* d_in, const int* in_sizes, int n_in,
                              void* d_out, int out_size)
{
    const float* element_mars = (const float*)d_in[1];
    const float* params       = (const float*)d_in[2];
    const int*   nids         = (const int*)d_in[3];
    const int*   cids         = (const int*)d_in[4];
    const int*   pids         = (const int*)d_in[5];
    float*       out          = (float*)d_out;

    const int N       = in_sizes[3];                    // nodes
    const int expCTAs = (ROWS * 16 + 255) / 256;        // 4096 per chunk
    const int gCTAs   = (N + NPC - 1) / NPC;            // 4096 per chunk
    const int mixCTAs = 2 * (expCTAs > gCTAs ? expCTAs : gCTAs);

    exp0_kernel<<<expCTAs, 256>>>(element_mars);

    mix_kernel<<<mixCTAs, 256>>>(element_mars, params, nids, cids, pids,
                                 out, N);

    gather1_kernel<<<gCTAs, 256>>>(params, nids, cids, pids, out, N);
}